// round 9
// baseline (speedup 1.0000x reference)
#include <cuda_runtime.h>

#define BN 64
#define CN 32
#define HN 80
#define WN 80
#define LN 6400
#define HEADSN 8
#define NCH 25
#define CHK 256
#define INV_PI 0.31830988618379067f

typedef unsigned long long u64;

__device__ __forceinline__ u64 pk2(float lo, float hi) {
    u64 r; asm("mov.b64 %0,{%1,%2};" : "=l"(r) : "f"(lo), "f"(hi)); return r;
}
__device__ __forceinline__ void upk2(u64 a, float& lo, float& hi) {
    asm("mov.b64 {%0,%1},%2;" : "=f"(lo), "=f"(hi) : "l"(a));
}
__device__ __forceinline__ u64 fma2_(u64 a, u64 b, u64 c) {
    u64 d; asm("fma.rn.f32x2 %0,%1,%2,%3;" : "=l"(d) : "l"(a), "l"(b), "l"(c)); return d;
}
__device__ __forceinline__ u64 add2_(u64 a, u64 b) {
    u64 d; asm("add.rn.f32x2 %0,%1,%2;" : "=l"(d) : "l"(a), "l"(b)); return d;
}
__device__ __forceinline__ u64 mul2_(u64 a, u64 b) {
    u64 d; asm("mul.rn.f32x2 %0,%1,%2;" : "=l"(d) : "l"(a), "l"(b)); return d;
}
__device__ __forceinline__ u64 shfl2(u64 a, int m) {
    float lo, hi; upk2(a, lo, hi);
    lo = __shfl_xor_sync(0xffffffffu, lo, m);
    hi = __shfl_xor_sync(0xffffffffu, hi, m);
    return pk2(lo, hi);
}

// ---------------- device scratch ----------------
static __device__ float g_vbuf[(size_t)BN * LN * CN];
static __device__ float g_f1[(size_t)BN * CN * LN];
static __device__ float g_f2[(size_t)BN * CN * LN];
static __device__ float g_part_la[BN * NCH * HEADSN * 16];
static __device__ float g_part_x[BN * NCH * HEADSN * 24];
static __device__ float g_pf_sum[2 * BN * NCH * 32];
static __device__ float g_pf_max[2 * BN * NCH * 32];
static __device__ float g_s1[BN * CN * CN];
static __device__ float g_s2[BN * CN * CN];
static __device__ float g_pooled1[BN * 2 * LN];
static __device__ float g_pooled2[BN * 2 * LN];
static __device__ float g_y2a[BN * LN];
static __device__ float g_y2b[BN * LN];
static __device__ float g_gstat[BN * 2 * 2];

// ================= K1: LA pass1 — tiled k/v GEMM, in-lane Gram, store v =================
#define LA1_SMEM (32768 + 8192 + 8192 + 2048)
__global__ __launch_bounds__(128) void k_la_pass1(const float* __restrict__ rgb,
                                                  const float* __restrict__ qkvw) {
    extern __shared__ __align__(16) char sm1[];
    float (*xsh)[256] = (float(*)[256])sm1;
    u64* kT = (u64*)(sm1 + 32768);
    u64* vT = (u64*)(sm1 + 40960);
    float* accsh = (float*)(sm1 + 49152);   // [4*8][16]
    const int b = blockIdx.y, ch = blockIdx.x, tid = threadIdx.x;
    const int warp = tid >> 5, lane = tid & 31;
    const int pg = lane >> 3, cg = lane & 7;
    const int l0b = ch * CHK;
    const float* xr = rgb + (size_t)b * CN * LN + l0b;
    for (int i = tid; i < 2048; i += 128) {
        int c = i >> 6, p4 = i & 63;
        *(float4*)&xsh[c][p4 * 4] = *(const float4*)(xr + (size_t)c * LN + p4 * 4);
    }
    for (int i = tid; i < 1024; i += 128) {
        int c = i >> 5, r = i & 31;
        float wk = qkvw[(32 + r) * 32 + c];
        float wv = qkvw[(64 + r) * 32 + c];
        kT[i] = pk2(wk, wk);
        vT[i] = pk2(wv, wv);
    }
    __syncthreads();
    float ps[16];
#pragma unroll
    for (int i = 0; i < 16; i++) ps[i] = 0.f;
    const int wb = warp * 32;
    float* vg = g_vbuf + ((size_t)b * LN + l0b) * 32;
#pragma unroll
    for (int t = 0; t < 2; t++) {
        u64 ka[16], va[16];
#pragma unroll
        for (int i = 0; i < 16; i++) { ka[i] = 0ull; va[i] = 0ull; }
#pragma unroll 4
        for (int c = 0; c < 32; c++) {
            u64 xv[4];
#pragma unroll
            for (int i = 0; i < 4; i++)
                xv[i] = *(const u64*)&xsh[c][2 * (wb + t * 16 + pg + 4 * i)];
            u64 wk[4], wv[4];
#pragma unroll
            for (int j = 0; j < 4; j++) { wk[j] = kT[c * 32 + 4 * cg + j]; wv[j] = vT[c * 32 + 4 * cg + j]; }
#pragma unroll
            for (int j = 0; j < 4; j++)
#pragma unroll
                for (int i = 0; i < 4; i++) {
                    ka[j * 4 + i] = fma2_(wk[j], xv[i], ka[j * 4 + i]);
                    va[j * 4 + i] = fma2_(wv[j], xv[i], va[j * 4 + i]);
                }
        }
#pragma unroll
        for (int i = 0; i < 4; i++) {
            int p = wb + t * 16 + pg + 4 * i;
            float vlo[4], vhi[4];
#pragma unroll
            for (int j = 0; j < 4; j++) upk2(va[j * 4 + i], vlo[j], vhi[j]);
            *(float4*)(vg + (size_t)(2 * p) * 32 + 4 * cg) = make_float4(vlo[0], vlo[1], vlo[2], vlo[3]);
            *(float4*)(vg + (size_t)(2 * p + 1) * 32 + 4 * cg) = make_float4(vhi[0], vhi[1], vhi[2], vhi[3]);
            u64 ss = mul2_(ka[i], ka[i]);
            ss = fma2_(ka[4 + i], ka[4 + i], ss);
            ss = fma2_(ka[8 + i], ka[8 + i], ss);
            ss = fma2_(ka[12 + i], ka[12 + i], ss);
            float s0, s1; upk2(ss, s0, s1);
            u64 knp = pk2(rsqrtf(s0), rsqrtf(s1));
#pragma unroll
            for (int d = 0; d < 4; d++) {
                u64 khd = mul2_(ka[d * 4 + i], knp);
#pragma unroll
                for (int e = 0; e < 4; e++) {
                    float a, bb; upk2(mul2_(khd, va[e * 4 + i]), a, bb);
                    ps[d * 4 + e] += a + bb;
                }
            }
        }
    }
#pragma unroll
    for (int i = 0; i < 16; i++) {
        ps[i] += __shfl_xor_sync(0xffffffffu, ps[i], 8);
        ps[i] += __shfl_xor_sync(0xffffffffu, ps[i], 16);
    }
    if (pg == 0) {
#pragma unroll
        for (int i = 0; i < 16; i++) accsh[(warp * 8 + cg) * 16 + i] = ps[i];
    }
    __syncthreads();
    {
        const int h = tid >> 4, de = tid & 15;
        float s = accsh[(0 + h) * 16 + de] + accsh[(8 + h) * 16 + de]
                + accsh[(16 + h) * 16 + de] + accsh[(24 + h) * 16 + de];
        g_part_la[(size_t)(b * NCH + ch) * 128 + tid] = s;
    }
}

// ================= K2: XCA pass1 — tiled q/k GEMM, in-lane Gram/norm partials =================
#define XCA1_SMEM (32768 + 8192 + 8192 + 3072)
__global__ __launch_bounds__(128) void k_xca_pass1(const float* __restrict__ freq,
                                                   const float* __restrict__ qkvw) {
    extern __shared__ __align__(16) char sm2[];
    float (*xsh)[256] = (float(*)[256])sm2;
    u64* qT = (u64*)(sm2 + 32768);
    u64* kT = (u64*)(sm2 + 40960);
    float* accsh = (float*)(sm2 + 49152);   // [4*8][24]
    const int b = blockIdx.y, ch = blockIdx.x, tid = threadIdx.x;
    const int warp = tid >> 5, lane = tid & 31;
    const int pg = lane >> 3, cg = lane & 7;
    const int l0b = ch * CHK;
    const float* xr = freq + (size_t)b * CN * LN + l0b;
    for (int i = tid; i < 2048; i += 128) {
        int c = i >> 6, p4 = i & 63;
        *(float4*)&xsh[c][p4 * 4] = *(const float4*)(xr + (size_t)c * LN + p4 * 4);
    }
    for (int i = tid; i < 1024; i += 128) {
        int c = i >> 5, r = i & 31;
        float wq = qkvw[r * 32 + c];
        float wk = qkvw[(32 + r) * 32 + c];
        qT[i] = pk2(wq, wq);
        kT[i] = pk2(wk, wk);
    }
    __syncthreads();
    float ps[24];
#pragma unroll
    for (int i = 0; i < 24; i++) ps[i] = 0.f;
    const int wb = warp * 32;
#pragma unroll
    for (int t = 0; t < 2; t++) {
        u64 qa[16], ka[16];
#pragma unroll
        for (int i = 0; i < 16; i++) { qa[i] = 0ull; ka[i] = 0ull; }
#pragma unroll 4
        for (int c = 0; c < 32; c++) {
            u64 xv[4];
#pragma unroll
            for (int i = 0; i < 4; i++)
                xv[i] = *(const u64*)&xsh[c][2 * (wb + t * 16 + pg + 4 * i)];
            u64 wq[4], wk[4];
#pragma unroll
            for (int j = 0; j < 4; j++) { wq[j] = qT[c * 32 + 4 * cg + j]; wk[j] = kT[c * 32 + 4 * cg + j]; }
#pragma unroll
            for (int j = 0; j < 4; j++)
#pragma unroll
                for (int i = 0; i < 4; i++) {
                    qa[j * 4 + i] = fma2_(wq[j], xv[i], qa[j * 4 + i]);
                    ka[j * 4 + i] = fma2_(wk[j], xv[i], ka[j * 4 + i]);
                }
        }
#pragma unroll
        for (int i = 0; i < 4; i++) {
#pragma unroll
            for (int d = 0; d < 4; d++)
#pragma unroll
                for (int e = 0; e < 4; e++) {
                    float a, bb; upk2(mul2_(qa[d * 4 + i], ka[e * 4 + i]), a, bb);
                    ps[d * 4 + e] += a + bb;
                }
#pragma unroll
            for (int d = 0; d < 4; d++) {
                float a, bb;
                upk2(mul2_(qa[d * 4 + i], qa[d * 4 + i]), a, bb); ps[16 + d] += a + bb;
                upk2(mul2_(ka[d * 4 + i], ka[d * 4 + i]), a, bb); ps[20 + d] += a + bb;
            }
        }
    }
#pragma unroll
    for (int i = 0; i < 24; i++) {
        ps[i] += __shfl_xor_sync(0xffffffffu, ps[i], 8);
        ps[i] += __shfl_xor_sync(0xffffffffu, ps[i], 16);
    }
    if (pg == 0) {
#pragma unroll
        for (int i = 0; i < 24; i++) accsh[(warp * 8 + cg) * 24 + i] = ps[i];
    }
    __syncthreads();
    for (int i = tid; i < 192; i += 128) {
        const int h = i / 24, j = i % 24;
        float s = accsh[(0 + h) * 24 + j] + accsh[(8 + h) * 24 + j]
                + accsh[(16 + h) * 24 + j] + accsh[(24 + h) * 24 + j];
        g_part_x[(size_t)(b * NCH + ch) * 192 + i] = s;
    }
}

// ================= K3: LA pass2 — tiled q GEMM, head math + dconv, proj, pool =================
#define LA2_SMEM 56864
__global__ __launch_bounds__(128) void k_la_pass2(const float* __restrict__ rgb,
                                                  const float* __restrict__ qkvw,
                                                  const float* __restrict__ pw,
                                                  const float* __restrict__ pb,
                                                  const float* __restrict__ dw) {
    extern __shared__ __align__(16) char sm3[];
    float (*buf)[256] = (float(*)[256])sm3;        // phase A: x tile
    float* buff = (float*)sm3;                     // phase B: v halo 264x36
    u64* ybuf = (u64*)sm3;                         // phase C: y tile [128 pairs][33]
    u64* qT = (u64*)(sm3 + 38016);
    u64* pT = (u64*)(sm3 + 46208);
    u64* attnsh = (u64*)(sm3 + 54400);
    float* pbsh = (float*)(sm3 + 55424);
    float* dwsh = (float*)(sm3 + 55552);
    float* poolsh = (float*)(sm3 + 55840);         // [4][32][2]
    const int b = blockIdx.y, ch = blockIdx.x, tid = threadIdx.x;
    const int warp = tid >> 5, lane = tid & 31;
    const int pg = lane >> 3, cg = lane & 7;
    const int l0b = ch * CHK;
    const float* xr = rgb + (size_t)b * CN * LN + l0b;
    for (int i = tid; i < 2048; i += 128) {
        int c = i >> 6, p4 = i & 63;
        *(float4*)&buf[c][p4 * 4] = *(const float4*)(xr + (size_t)c * LN + p4 * 4);
    }
    for (int i = tid; i < 1024; i += 128) {
        float wq = qkvw[(i & 31) * 32 + (i >> 5)];
        float wp = pw[(i & 31) * 32 + (i >> 5)];
        qT[i] = pk2(wq, wq);
        pT[i] = pk2(wp, wp);
    }
    {
        float s = 0.f;
        for (int c2 = 0; c2 < NCH; c2++) s += g_part_la[(size_t)(b * NCH + c2) * 128 + tid];
        attnsh[tid] = pk2(s, s);
    }
    if (tid < 72) dwsh[tid] = dw[tid];
    if (tid < 32) pbsh[tid] = pb[tid];
    __syncthreads();
    const int wb = warp * 32;
    // q GEMM: acc[j*8+i], pairs p = wb + pg + 4i
    u64 acc[32];
#pragma unroll
    for (int r = 0; r < 32; r++) acc[r] = 0ull;
#pragma unroll 4
    for (int c = 0; c < 32; c++) {
        u64 xv[8];
#pragma unroll
        for (int i = 0; i < 8; i++)
            xv[i] = *(const u64*)&buf[c][2 * (wb + pg + 4 * i)];
        u64 w[4];
#pragma unroll
        for (int j = 0; j < 4; j++) w[j] = qT[c * 32 + 4 * cg + j];
#pragma unroll
        for (int j = 0; j < 4; j++)
#pragma unroll
            for (int i = 0; i < 8; i++)
                acc[j * 8 + i] = fma2_(w[j], xv[i], acc[j * 8 + i]);
    }
    __syncthreads();
    // stage v halo (264 rows x stride 36)
    for (int i = tid; i < 264 * 8; i += 128) {
        int r = i >> 3, c4 = i & 7;
        int gl = l0b - 4 + r;
        float4 v = (gl >= 0 && gl < LN) ? *(const float4*)(g_vbuf + ((size_t)b * LN + gl) * 32 + c4 * 4)
                                        : make_float4(0.f, 0.f, 0.f, 0.f);
        *(float4*)(buff + r * 36 + c4 * 4) = v;
    }
    __syncthreads();
    // per-pair head math (head = cg, in-lane)
    u64 ar[16];
#pragma unroll
    for (int k = 0; k < 16; k++) ar[k] = attnsh[cg * 16 + k];
    float dwr[9];
#pragma unroll
    for (int t = 0; t < 9; t++) dwr[t] = dwsh[cg * 9 + t];
    const u64 HALFP = pk2(0.5f, 0.5f);
#pragma unroll
    for (int i = 0; i < 8; i++) {
        int p = wb + pg + 4 * i;
        u64 q0 = acc[i], q1 = acc[8 + i], q2 = acc[16 + i], q3 = acc[24 + i];
        u64 ss = mul2_(q0, q0);
        ss = fma2_(q1, q1, ss); ss = fma2_(q2, q2, ss); ss = fma2_(q3, q3, ss);
        float s0, s1; upk2(ss, s0, s1);
        u64 qnp = pk2(rsqrtf(s0) * INV_PI, rsqrtf(s1) * INV_PI);
        float dc0[4] = {0.f, 0.f, 0.f, 0.f}, dc1[4] = {0.f, 0.f, 0.f, 0.f};
        u64 vcp[4];
        float4 aR = *(float4*)(buff + (2 * p) * 36 + 4 * cg);
#pragma unroll
        for (int t9 = 0; t9 < 9; t9++) {
            float4 nb = *(float4*)(buff + (2 * p + t9 + 1) * 36 + 4 * cg);
            float wd = dwr[t9];
            dc0[0] += wd * aR.x; dc0[1] += wd * aR.y; dc0[2] += wd * aR.z; dc0[3] += wd * aR.w;
            dc1[0] += wd * nb.x; dc1[1] += wd * nb.y; dc1[2] += wd * nb.z; dc1[3] += wd * nb.w;
            if (t9 == 4) {
                vcp[0] = pk2(aR.x, nb.x); vcp[1] = pk2(aR.y, nb.y);
                vcp[2] = pk2(aR.z, nb.z); vcp[3] = pk2(aR.w, nb.w);
            }
            aR = nb;
        }
        u64 o[4];
#pragma unroll
        for (int e = 0; e < 4; e++) {
            u64 t = mul2_(q0, ar[e]);
            t = fma2_(q1, ar[4 + e], t);
            t = fma2_(q2, ar[8 + e], t);
            t = fma2_(q3, ar[12 + e], t);
            o[e] = fma2_(qnp, t, mul2_(HALFP, vcp[e]));
        }
        u64 os = mul2_(o[0], o[0]);
        os = fma2_(o[1], o[1], os); os = fma2_(o[2], o[2], os); os = fma2_(o[3], o[3], os);
        float o0, o1; upk2(os, o0, o1);
        u64 onp = pk2(rsqrtf(o0), rsqrtf(o1));
#pragma unroll
        for (int e = 0; e < 4; e++)
            acc[e * 8 + i] = fma2_(o[e], onp, pk2(dc0[e], dc1[e]));
    }
    __syncthreads();
    // y tile [pair][33] (halo dead)
#pragma unroll
    for (int j = 0; j < 4; j++)
#pragma unroll
        for (int i = 0; i < 8; i++)
            ybuf[(wb + pg + 4 * i) * 33 + 4 * cg + j] = acc[j * 8 + i];
    __syncthreads();
    // proj GEMM (in-outer over jj)
    u64 pa[32];
#pragma unroll
    for (int j = 0; j < 4; j++) {
        u64 init = pk2(pbsh[4 * cg + j], pbsh[4 * cg + j]);
#pragma unroll
        for (int i = 0; i < 8; i++) pa[j * 8 + i] = init;
    }
#pragma unroll 4
    for (int jj = 0; jj < 32; jj++) {
        u64 yv[8];
#pragma unroll
        for (int i = 0; i < 8; i++)
            yv[i] = ybuf[(wb + pg + 4 * i) * 33 + jj];
        u64 w[4];
#pragma unroll
        for (int j = 0; j < 4; j++) w[j] = pT[jj * 32 + 4 * cg + j];
#pragma unroll
        for (int j = 0; j < 4; j++)
#pragma unroll
            for (int i = 0; i < 8; i++)
                pa[j * 8 + i] = fma2_(w[j], yv[i], pa[j * 8 + i]);
    }
    float csum[4], cmax[4];
#pragma unroll
    for (int j = 0; j < 4; j++) { csum[j] = 0.f; cmax[j] = -1e30f; }
#pragma unroll
    for (int j = 0; j < 4; j++)
#pragma unroll
        for (int i = 0; i < 8; i++) {
            u64 a = pa[j * 8 + i];
            *(u64*)(g_f1 + (size_t)b * CN * LN + (size_t)(4 * cg + j) * LN + l0b + 2 * (wb + pg + 4 * i)) = a;
            float s0, s1; upk2(a, s0, s1);
            csum[j] += s0 + s1;
            cmax[j] = fmaxf(cmax[j], fmaxf(s0, s1));
        }
#pragma unroll
    for (int j = 0; j < 4; j++) {
        csum[j] += __shfl_xor_sync(0xffffffffu, csum[j], 8);
        csum[j] += __shfl_xor_sync(0xffffffffu, csum[j], 16);
        cmax[j] = fmaxf(cmax[j], __shfl_xor_sync(0xffffffffu, cmax[j], 8));
        cmax[j] = fmaxf(cmax[j], __shfl_xor_sync(0xffffffffu, cmax[j], 16));
    }
    if (pg == 0) {
#pragma unroll
        for (int j = 0; j < 4; j++) {
            poolsh[(warp * 32 + 4 * cg + j) * 2] = csum[j];
            poolsh[(warp * 32 + 4 * cg + j) * 2 + 1] = cmax[j];
        }
    }
    __syncthreads();
    if (tid < 32) {
        float s = poolsh[tid * 2] + poolsh[(32 + tid) * 2] + poolsh[(64 + tid) * 2] + poolsh[(96 + tid) * 2];
        float m = fmaxf(fmaxf(poolsh[tid * 2 + 1], poolsh[(32 + tid) * 2 + 1]),
                        fmaxf(poolsh[(64 + tid) * 2 + 1], poolsh[(96 + tid) * 2 + 1]));
        g_pf_sum[((size_t)b * NCH + ch) * 32 + tid] = s;
        g_pf_max[((size_t)b * NCH + ch) * 32 + tid] = m;
    }
}

// ================= K4: XCA pass2 — tiled v GEMM, in-lane attn, proj, pool =================
#define XCA2_SMEM 52352
__global__ __launch_bounds__(128) void k_xca_pass2(const float* __restrict__ freq,
                                                   const float* __restrict__ qkvw,
                                                   const float* __restrict__ pw,
                                                   const float* __restrict__ pb,
                                                   const float* __restrict__ temp) {
    extern __shared__ __align__(16) char sm4[];
    float (*buf)[256] = (float(*)[256])sm4;
    u64* ybuf = (u64*)sm4;
    u64* vT = (u64*)(sm4 + 33792);
    u64* pT = (u64*)(sm4 + 41984);
    u64* attnsh = (u64*)(sm4 + 50176);
    float* pbsh = (float*)(sm4 + 51200);
    float* poolsh = (float*)(sm4 + 51328);
    const int b = blockIdx.y, ch = blockIdx.x, tid = threadIdx.x;
    const int warp = tid >> 5, lane = tid & 31;
    const int pg = lane >> 3, cg = lane & 7;
    const int l0b = ch * CHK;
    const float* xr = freq + (size_t)b * CN * LN + l0b;
    for (int i = tid; i < 2048; i += 128) {
        int c = i >> 6, p4 = i & 63;
        *(float4*)&buf[c][p4 * 4] = *(const float4*)(xr + (size_t)c * LN + p4 * 4);
    }
    for (int i = tid; i < 1024; i += 128) {
        float wv = qkvw[64 * 32 + (i & 31) * 32 + (i >> 5)];
        float wp = pw[(i & 31) * 32 + (i >> 5)];
        vT[i] = pk2(wv, wv);
        pT[i] = pk2(wp, wp);
    }
    if (tid < 32) pbsh[tid] = pb[tid];
    if (tid < 32) {   // folded attn softmax
        const int h = tid >> 2, d = tid & 3;
        const float* base = g_part_x + (size_t)b * NCH * 192 + h * 24;
        float qk[4] = {0.f, 0.f, 0.f, 0.f}, qq = 0.f, kk[4] = {0.f, 0.f, 0.f, 0.f};
        for (int c2 = 0; c2 < NCH; c2++) {
            const float* pc = base + (size_t)c2 * 192;
            qk[0] += pc[d * 4 + 0]; qk[1] += pc[d * 4 + 1]; qk[2] += pc[d * 4 + 2]; qk[3] += pc[d * 4 + 3];
            qq += pc[16 + d];
            kk[0] += pc[20]; kk[1] += pc[21]; kk[2] += pc[22]; kk[3] += pc[23];
        }
        float nq = fmaxf(sqrtf(qq), 1e-12f);
        float t = temp[h];
        float a[4], m = -1e30f;
#pragma unroll
        for (int e = 0; e < 4; e++) {
            a[e] = qk[e] / (nq * fmaxf(sqrtf(kk[e]), 1e-12f)) * t;
            m = fmaxf(m, a[e]);
        }
        float sum = 0.f;
#pragma unroll
        for (int e = 0; e < 4; e++) { a[e] = expf(a[e] - m); sum += a[e]; }
        float inv = 1.f / sum;
#pragma unroll
        for (int e = 0; e < 4; e++) {
            float v = a[e] * inv;
            attnsh[h * 16 + d * 4 + e] = pk2(v, v);
        }
    }
    __syncthreads();
    const int wb = warp * 32;
    u64 acc[32];
#pragma unroll
    for (int r = 0; r < 32; r++) acc[r] = 0ull;
#pragma unroll 4
    for (int c = 0; c < 32; c++) {
        u64 xv[8];
#pragma unroll
        for (int i = 0; i < 8; i++)
            xv[i] = *(const u64*)&buf[c][2 * (wb + pg + 4 * i)];
        u64 w[4];
#pragma unroll
        for (int j = 0; j < 4; j++) w[j] = vT[c * 32 + 4 * cg + j];
#pragma unroll
        for (int j = 0; j < 4; j++)
#pragma unroll
            for (int i = 0; i < 8; i++)
                acc[j * 8 + i] = fma2_(w[j], xv[i], acc[j * 8 + i]);
    }
    // attn apply (in-lane head)
    u64 ar[16];
#pragma unroll
    for (int k = 0; k < 16; k++) ar[k] = attnsh[cg * 16 + k];
#pragma unroll
    for (int i = 0; i < 8; i++) {
        u64 v0 = acc[i], v1 = acc[8 + i], v2 = acc[16 + i], v3 = acc[24 + i];
#pragma unroll
        for (int d = 0; d < 4; d++) {
            u64 o = mul2_(ar[d * 4 + 0], v0);
            o = fma2_(ar[d * 4 + 1], v1, o);
            o = fma2_(ar[d * 4 + 2], v2, o);
            o = fma2_(ar[d * 4 + 3], v3, o);
            acc[d * 8 + i] = o;
        }
    }
    __syncthreads();
#pragma unroll
    for (int j = 0; j < 4; j++)
#pragma unroll
        for (int i = 0; i < 8; i++)
            ybuf[(wb + pg + 4 * i) * 33 + 4 * cg + j] = acc[j * 8 + i];
    __syncthreads();
    u64 pa[32];
#pragma unroll
    for (int j = 0; j < 4; j++) {
        u64 init = pk2(pbsh[4 * cg + j], pbsh[4 * cg + j]);
#pragma unroll
        for (int i = 0; i < 8; i++) pa[j * 8 + i] = init;
    }
#pragma unroll 4
    for (int jj = 0; jj < 32; jj++) {
        u64 yv[8];
#pragma unroll
        for (int i = 0; i < 8; i++)
            yv[i] = ybuf[(wb + pg + 4 * i) * 33 + jj];
        u64 w[4];
#pragma unroll
        for (int j = 0; j < 4; j++) w[j] = pT[jj * 32 + 4 * cg + j];
#pragma unroll
        for (int j = 0; j < 4; j++)
#pragma unroll
            for (int i = 0; i < 8; i++)
                pa[j * 8 + i] = fma2_(w[j], yv[i], pa[j * 8 + i]);
    }
    float csum[4], cmax[4];
#pragma unroll
    for (int j = 0; j < 4; j++) { csum[j] = 0.f; cmax[j] = -1e30f; }
#pragma unroll
    for (int j = 0; j < 4; j++)
#pragma unroll
        for (int i = 0; i < 8; i++) {
            u64 a = pa[j * 8 + i];
            *(u64*)(g_f2 + (size_t)b * CN * LN + (size_t)(4 * cg + j) * LN + l0b + 2 * (wb + pg + 4 * i)) = a;
            float s0, s1; upk2(a, s0, s1);
            csum[j] += s0 + s1;
            cmax[j] = fmaxf(cmax[j], fmaxf(s0, s1));
        }
#pragma unroll
    for (int j = 0; j < 4; j++) {
        csum[j] += __shfl_xor_sync(0xffffffffu, csum[j], 8);
        csum[j] += __shfl_xor_sync(0xffffffffu, csum[j], 16);
        cmax[j] = fmaxf(cmax[j], __shfl_xor_sync(0xffffffffu, cmax[j], 8));
        cmax[j] = fmaxf(cmax[j], __shfl_xor_sync(0xffffffffu, cmax[j], 16));
    }
    if (pg == 0) {
#pragma unroll
        for (int j = 0; j < 4; j++) {
            poolsh[(warp * 32 + 4 * cg + j) * 2] = csum[j];
            poolsh[(warp * 32 + 4 * cg + j) * 2 + 1] = cmax[j];
        }
    }
    __syncthreads();
    if (tid < 32) {
        float s = poolsh[tid * 2] + poolsh[(32 + tid) * 2] + poolsh[(64 + tid) * 2] + poolsh[(96 + tid) * 2];
        float m = fmaxf(fmaxf(poolsh[tid * 2 + 1], poolsh[(32 + tid) * 2 + 1]),
                        fmaxf(poolsh[(64 + tid) * 2 + 1], poolsh[(96 + tid) * 2 + 1]));
        g_pf_sum[(size_t)(BN * NCH * 32) + ((size_t)b * NCH + ch) * 32 + tid] = s;
        g_pf_max[(size_t)(BN * NCH * 32) + ((size_t)b * NCH + ch) * 32 + tid] = m;
    }
}

// ================= K5: channel MLPs + cross softmax =================
__global__ void k_cafm_vec(const float* __restrict__ a1w, const float* __restrict__ a1b,
                           const float* __restrict__ m1w, const float* __restrict__ m1b,
                           const float* __restrict__ a2w, const float* __restrict__ a2b,
                           const float* __restrict__ m2w, const float* __restrict__ m2b,
                           const float* __restrict__ a11w, const float* __restrict__ a11b,
                           const float* __restrict__ m11w, const float* __restrict__ m11b,
                           const float* __restrict__ a22w, const float* __restrict__ a22b,
                           const float* __restrict__ m22w, const float* __restrict__ m22b) {
    const int b = blockIdx.x, c = threadIdx.x;
    __shared__ float av1[32], mx1[32], av2[32], mx2[32];
    __shared__ float h1a[16], h1m[16], h2a[16], h2m[16];
    __shared__ float a1s[32], a2s[32];
    {
        float s1 = 0.f, m1 = -1e30f, s2 = 0.f, m2 = -1e30f;
        for (int chn = 0; chn < NCH; chn++) {
            s1 += g_pf_sum[((size_t)b * NCH + chn) * 32 + c];
            m1 = fmaxf(m1, g_pf_max[((size_t)b * NCH + chn) * 32 + c]);
            s2 += g_pf_sum[(size_t)(BN * NCH * 32) + ((size_t)b * NCH + chn) * 32 + c];
            m2 = fmaxf(m2, g_pf_max[(size_t)(BN * NCH * 32) + ((size_t)b * NCH + chn) * 32 + c]);
        }
        av1[c] = s1 * (1.f / LN); mx1[c] = m1;
        av2[c] = s2 * (1.f / LN); mx2[c] = m2;
    }
    __syncthreads();
    if (c < 16) {
        float s1 = a1b[c], s2 = m1b[c], s3 = a2b[c], s4 = m2b[c];
        for (int j = 0; j < 32; j++) {
            s1 += a1w[c * 32 + j] * av1[j];
            s2 += m1w[c * 32 + j] * mx1[j];
            s3 += a2w[c * 32 + j] * av2[j];
            s4 += m2w[c * 32 + j] * mx2[j];
        }
        h1a[c] = fmaxf(s1, 0.f); h1m[c] = fmaxf(s2, 0.f);
        h2a[c] = fmaxf(s3, 0.f); h2m[c] = fmaxf(s4, 0.f);
    }
    __syncthreads();
    {
        float s1 = a11b[c] + m11b[c];
        float s2 = a22b[c] + m22b[c];
        for (int j = 0; j < 16; j++) {
            s1 += a11w[c * 16 + j] * h1a[j] + m11w[c * 16 + j] * h1m[j];
            s2 += a22w[c * 16 + j] * h2a[j] + m22w[c * 16 + j] * h2m[j];
        }
        a1s[c] = s1; a2s[c] = s2;
    }
    __syncthreads();
    {
        float ac = a1s[c], m = -1e30f;
        for (int d = 0; d < 32; d++) m = fmaxf(m, ac * a2s[d]);
        float sum = 0.f;
        for (int d = 0; d < 32; d++) sum += expf(ac * a2s[d] - m);
        float inv = 1.f / sum;
        for (int d = 0; d < 32; d++) g_s1[(size_t)b * 1024 + c * 32 + d] = expf(ac * a2s[d] - m) * inv;
    }
    {
        float ac = a2s[c], m = -1e30f;
        for (int d = 0; d < 32; d++) m = fmaxf(m, ac * a1s[d]);
        float sum = 0.f;
        for (int d = 0; d < 32; d++) sum += expf(ac * a1s[d] - m);
        float inv = 1.f / sum;
        for (int d = 0; d < 32; d++) g_s2[(size_t)b * 1024 + c * 32 + d] = expf(ac * a1s[d] - m) * inv;
    }
}

// ================= K6: fused s@f + mean/max over C (tiled, both branches) =================
#define GP_SMEM (32768 + 8192)
__global__ __launch_bounds__(128) void k_gate_pool() {
    extern __shared__ __align__(16) char sm5[];
    float (*fbuf)[256] = (float(*)[256])sm5;
    u64* sTd = (u64*)(sm5 + 32768);
    const int b = blockIdx.y, ch = blockIdx.x, tid = threadIdx.x;
    const int warp = tid >> 5, lane = tid & 31;
    const int pg = lane >> 3, cg = lane & 7;
    const int l0b = ch * CHK;
    const int wb = warp * 32;
    const float* srcs[2] = { g_f1 + (size_t)b * CN * LN + l0b, g_f2 + (size_t)b * CN * LN + l0b };
    const float* wsrc[2] = { g_s1 + (size_t)b * 1024, g_s2 + (size_t)b * 1024 };
    float* dsts[2] = { g_pooled1 + (size_t)b * 2 * LN, g_pooled2 + (size_t)b * 2 * LN };
#pragma unroll
    for (int br = 0; br < 2; br++) {
        for (int i = tid; i < 2048; i += 128) {
            int c = i >> 6, p4 = i & 63;
            *(float4*)&fbuf[c][p4 * 4] = *(const float4*)(srcs[br] + (size_t)c * LN + p4 * 4);
        }
        for (int i = tid; i < 1024; i += 128) {
            float a = wsrc[br][(i & 31) * 32 + (i >> 5)];   // sT[d][c] = s[c][d]
            sTd[i] = pk2(a, a);
        }
        __syncthreads();
        u64 acc[32];
#pragma unroll
        for (int r = 0; r < 32; r++) acc[r] = 0ull;
#pragma unroll 4
        for (int d = 0; d < 32; d++) {
            u64 xv[8];
#pragma unroll
            for (int i = 0; i < 8; i++)
                xv[i] = *(const u64*)&fbuf[d][2 * (wb + pg + 4 * i)];
            u64 w[4];
#pragma unroll
            for (int j = 0; j < 4; j++) w[j] = sTd[d * 32 + 4 * cg + j];
#pragma unroll
            for (int j = 0; j < 4; j++)
#pragma unroll
                for (int i = 0; i < 8; i++)
                    acc[j * 8 + i] = fma2_(w[j], xv[i], acc[j * 8 + i]);
        }
#pragma unroll
        for (int i = 0; i < 8; i++) {
            u64 s = add2_(add2_(acc[i], acc[8 + i]), add2_(acc[16 + i], acc[24 + i]));
            float m0, m1;
            {
                float a0, a1, b0_, b1_, c0, c1, d0, d1;
                upk2(acc[i], a0, a1); upk2(acc[8 + i], b0_, b1_);
                upk2(acc[16 + i], c0, c1); upk2(acc[24 + i], d0, d1);
                m0 = fmaxf(fmaxf(a0, b0_), fmaxf(c0, d0));
                m1 = fmaxf(fmaxf(a1, b1_), fmaxf(c1, d1));
            }
            s = add2_(s, shfl2(s, 1));
            s = add2_(s, shfl2(s, 2));
            s = add2_(s, shfl2(s, 4));
            m0 = fmaxf(m0, __shfl_xor_sync(0xffffffffu, m0, 1));
            m0 = fmaxf(m0, __shfl_xor_sync(0xffffffffu, m0, 2));
            m0 = fmaxf(m0, __shfl_xor_sync(0xffffffffu, m0, 4));
            m1 = fmaxf(m1, __shfl_xor_sync(0xffffffffu, m1, 1));
            m1 = fmaxf(m1, __shfl_xor_sync(0xffffffffu, m1, 2));
            m1 = fmaxf(m1, __shfl_xor_sync(0xffffffffu, m1, 4));
            if (cg == 0) {
                int p = wb + pg + 4 * i;
                *(u64*)(dsts[br] + l0b + 2 * p) = mul2_(s, pk2(1.f / 32.f, 1.f / 32.f));
                *(u64*)(dsts[br] + LN + l0b + 2 * p) = pk2(m0, m1);
            }
        }
        __syncthreads();
    }
}

// ================= K7: fused conv1 + conv2 + softmax stats =================
__global__ __launch_bounds__(256) void k_gate_conv(const float* __restrict__ c1w, const float* __restrict__ c1b,
                                                   const float* __restrict__ c2w, const float* __restrict__ c2b) {
    const int b = blockIdx.x, gate = blockIdx.y, tid = threadIdx.x;
    __shared__ float y1s[LN];
    __shared__ float red[256];
    const float* pin = (gate ? g_pooled2 : g_pooled1) + (size_t)b * 2 * LN;
    float* yo = (gate ? g_y2b : g_y2a) + (size_t)b * LN;
    float w1[18];
#pragma unroll
    for (int i = 0; i < 18; i++) w1[i] = c1w[i];
    float b1 = c1b[0];
    float w2[9];
#pragma unroll
    for (int i = 0; i < 9; i++) w2[i] = c2w[i];
    float b2 = c2b[0];
    for (int p = tid; p < LN; p += 256) {
        int hh = p / WN, ww = p % WN;
        float acc = b1;
#pragma unroll
        for (int ci = 0; ci < 2; ci++)
#pragma unroll
            for (int kh = 0; kh < 3; kh++) {
                int ih = hh + kh - 1;
                if (ih < 0 || ih >= HN) continue;
#pragma unroll
                for (int kw = 0; kw < 3; kw++) {
                    int iw = ww + kw - 1;
                    if (iw < 0 || iw >= WN) continue;
                    acc += pin[(size_t)ci * LN + ih * WN + iw] * w1[(ci * 3 + kh) * 3 + kw];
                }
            }
        y1s[p] = fmaxf(acc, 0.f);
    }
    __syncthreads();
    float yl[25];
    float mloc = -1e30f;
    int idx = 0;
    for (int p = tid; p < LN; p += 256, idx++) {
        int hh = p / WN, ww = p % WN;
        float acc = b2;
#pragma unroll
        for (int kh = 0; kh < 3; kh++) {
            int ih = hh + kh - 1;
            if (ih < 0 || ih >= HN) continue;
#pragma unroll
            for (int kw = 0; kw < 3; kw++) {
                int iw = ww + kw - 1;
                if (iw < 0 || iw >= WN) continue;
                acc += y1s[ih * WN + iw] * w2[kh * 3 + kw];
            }
        }
        yo[p] = acc;
        yl[idx] = acc;
        mloc = fmaxf(mloc, acc);
    }
    red[tid] = mloc;
    __syncthreads();
    for (int o = 128; o > 0; o >>= 1) { if (tid < o) red[tid] = fmaxf(red[tid], red[tid + o]); __syncthreads(); }
    float gm = red[0];
    __syncthreads();
    float sloc = 0.f;
#pragma unroll
    for (int i = 0; i < 25; i++) sloc += expf(yl[i] - gm);
    red[tid] = sloc;
    __syncthreads();
    for (int o = 128; o > 0; o >>= 1) { if (tid < o) red[tid] += red[tid + o]; __syncthreads(); }
    if (tid == 0) { g_gstat[(b * 2 + gate) * 2] = gm; g_gstat[(b * 2 + gate) * 2 + 1] = red[0]; }
}

// ================= K8: final gated residual combine =================
__global__ __launch_bounds__(256) void k_final(float* __restrict__ out) {
    const int NT4 = BN * CN * LN / 4;
    int i4 = blockIdx.x * 256 + threadIdx.x;
    if (i4 >= NT4) return;
    size_t i = (size_t)i4 * 4;
    int b = (int)(i / (CN * LN));
    int rem = (int)(i - (size_t)b * CN * LN);
    int l = rem % LN;
    float4 f1v = *(const float4*)(g_f1 + i);
    float4 f2v = *(const float4*)(g_f2 + i);
    float4 y1v = *(const float4*)(g_y2a + (size_t)b * LN + l);
    float4 y2v = *(const float4*)(g_y2b + (size_t)b * LN + l);
    float m1 = g_gstat[b * 4 + 0], s1i = 1.f / g_gstat[b * 4 + 1];
    float m2 = g_gstat[b * 4 + 2], s2i = 1.f / g_gstat[b * 4 + 3];
    float4 o;
    o.x = f1v.x * (1.f + expf(y1v.x - m1) * s1i) + f2v.x * (1.f + expf(y2v.x - m2) * s2i);
    o.y = f1v.y * (1.f + expf(y1v.y - m1) * s1i) + f2v.y * (1.f + expf(y2v.y - m2) * s2i);
    o.z = f1v.z * (1.f + expf(y1v.z - m1) * s1i) + f2v.z * (1.f + expf(y2v.z - m2) * s2i);
    o.w = f1v.w * (1.f + expf(y1v.w - m1) * s1i) + f2v.w * (1.f + expf(y2v.w - m2) * s2i);
    *(float4*)(out + i) = o;
}

// ---------------- launch ----------------
extern "C" void kernel_launch(void* const* d_in, const int* in_sizes, int n_in,
                              void* d_out, int out_size) {
    const float* rgb     = (const float*)d_in[0];
    const float* freq    = (const float*)d_in[1];
    const float* la_qkv  = (const float*)d_in[2];
    const float* la_pw   = (const float*)d_in[3];
    const float* la_pb   = (const float*)d_in[4];
    const float* la_dw   = (const float*)d_in[5];
    const float* xa_qkv  = (const float*)d_in[6];
    const float* xa_temp = (const float*)d_in[7];
    const float* xa_pw   = (const float*)d_in[8];
    const float* xa_pb   = (const float*)d_in[9];
    const float* c1w     = (const float*)d_in[10];
    const float* c1b     = (const float*)d_in[11];
    const float* c2w     = (const float*)d_in[12];
    const float* c2b     = (const float*)d_in[13];
    const float* avg1_w  = (const float*)d_in[14];
    const float* avg1_b  = (const float*)d_in[15];
    const float* max1_w  = (const float*)d_in[16];
    const float* max1_b  = (const float*)d_in[17];
    const float* avg2_w  = (const float*)d_in[18];
    const float* avg2_b  = (const float*)d_in[19];
    const float* max2_w  = (const float*)d_in[20];
    const float* max2_b  = (const float*)d_in[21];
    const float* avg11_w = (const float*)d_in[22];
    const float* avg11_b = (const float*)d_in[23];
    const float* max11_w = (const float*)d_in[24];
    const float* max11_b = (const float*)d_in[25];
    const float* avg22_w = (const float*)d_in[26];
    const float* avg22_b = (const float*)d_in[27];
    const float* max22_w = (const float*)d_in[28];
    const float* max22_b = (const float*)d_in[29];
    float* out = (float*)d_out;

    static int smem_set = 0;
    if (!smem_set) {
        cudaFuncSetAttribute(k_la_pass1, cudaFuncAttributeMaxDynamicSharedMemorySize, LA1_SMEM);
        cudaFuncSetAttribute(k_xca_pass1, cudaFuncAttributeMaxDynamicSharedMemorySize, XCA1_SMEM);
        cudaFuncSetAttribute(k_la_pass2, cudaFuncAttributeMaxDynamicSharedMemorySize, LA2_SMEM);
        cudaFuncSetAttribute(k_xca_pass2, cudaFuncAttributeMaxDynamicSharedMemorySize, XCA2_SMEM);
        smem_set = 1;
    }

    dim3 gBL(NCH, BN);
    k_la_pass1<<<gBL, 128, LA1_SMEM>>>(rgb, la_qkv);
    k_xca_pass1<<<gBL, 128, XCA1_SMEM>>>(freq, xa_qkv);
    k_la_pass2<<<gBL, 128, LA2_SMEM>>>(rgb, la_qkv, la_pw, la_pb, la_dw);
    k_xca_pass2<<<gBL, 128, XCA2_SMEM>>>(freq, xa_qkv, xa_pw, xa_pb, xa_temp);
    k_cafm_vec<<<BN, 32>>>(avg1_w, avg1_b, max1_w, max1_b,
                           avg2_w, avg2_b, max2_w, max2_b,
                           avg11_w, avg11_b, max11_w, max11_b,
                           avg22_w, avg22_b, max22_w, max22_b);
    k_gate_pool<<<gBL, 128, GP_SMEM>>>();
    k_gate_conv<<<dim3(BN, 2), 256>>>(c1w, c1b, c2w, c2b);
    k_final<<<(BN * CN * LN / 4 + 255) / 256, 256>>>(out);
}

// round 12
// speedup vs baseline: 1.3722x; 1.3722x over previous
#include <cuda_runtime.h>

#define BN 64
#define CN 32
#define HN 80
#define WN 80
#define LN 6400
#define HEADSN 8
#define NCH 25
#define CHK 256
#define INV_PI 0.31830988618379067f

typedef unsigned long long u64;

__device__ __forceinline__ u64 pk2(float lo, float hi) {
    u64 r; asm("mov.b64 %0,{%1,%2};" : "=l"(r) : "f"(lo), "f"(hi)); return r;
}
__device__ __forceinline__ void upk2(u64 a, float& lo, float& hi) {
    asm("mov.b64 {%0,%1},%2;" : "=f"(lo), "=f"(hi) : "l"(a));
}
__device__ __forceinline__ u64 fma2_(u64 a, u64 b, u64 c) {
    u64 d; asm("fma.rn.f32x2 %0,%1,%2,%3;" : "=l"(d) : "l"(a), "l"(b), "l"(c)); return d;
}
__device__ __forceinline__ u64 add2_(u64 a, u64 b) {
    u64 d; asm("add.rn.f32x2 %0,%1,%2;" : "=l"(d) : "l"(a), "l"(b)); return d;
}
__device__ __forceinline__ u64 mul2_(u64 a, u64 b) {
    u64 d; asm("mul.rn.f32x2 %0,%1,%2;" : "=l"(d) : "l"(a), "l"(b)); return d;
}

// ---------------- device scratch ----------------
static __device__ float g_vbuf[(size_t)BN * LN * CN];
static __device__ float g_f1[(size_t)BN * CN * LN];
static __device__ float g_f2[(size_t)BN * CN * LN];
static __device__ float g_part_la[BN * NCH * HEADSN * 16];
static __device__ float g_part_x[BN * NCH * HEADSN * 24];
static __device__ float g_pf_sum[2 * BN * NCH * 32];
static __device__ float g_pf_max[2 * BN * NCH * 32];
static __device__ float g_s1[BN * CN * CN];
static __device__ float g_s2[BN * CN * CN];
static __device__ float g_pooled1[BN * 2 * LN];
static __device__ float g_pooled2[BN * 2 * LN];
static __device__ float g_y2a[BN * LN];
static __device__ float g_y2b[BN * LN];
static __device__ float g_gstat[BN * 2 * 2];

// ---------------- K1: LA pass1 — khat(x)v Gram partials + store v (R8-proven) ----------------
__global__ __launch_bounds__(128) void k_la_pass1(const float* __restrict__ rgb,
                                                  const float* __restrict__ qkvw) {
    __shared__ __align__(16) u64 wdup[64 * 32];
    __shared__ float accsh[4][4][HEADSN][16];
    const int b = blockIdx.y, ch = blockIdx.x, tid = threadIdx.x;
    const int warp = tid >> 5, lane = tid & 31;
    for (int i = tid; i < 64 * 32; i += 128) { float w = qkvw[32 * 32 + i]; wdup[i] = pk2(w, w); }
    __syncthreads();
    const int l0 = ch * CHK + 2 * tid;
    const float* xr = rgb + (size_t)b * CN * LN;
    u64 xp[32];
#pragma unroll
    for (int c = 0; c < 32; c++) xp[c] = *(const u64*)(xr + (size_t)c * LN + l0);
    float* vg0 = g_vbuf + ((size_t)b * LN + l0) * 32;
#pragma unroll
    for (int h = 0; h < HEADSN; h++) {
        u64 kp[4], vp[4];
#pragma unroll
        for (int d = 0; d < 4; d++) {
            const ulonglong2* wk2 = (const ulonglong2*)&wdup[(h * 4 + d) * 32];
            const ulonglong2* wv2 = (const ulonglong2*)&wdup[(32 + h * 4 + d) * 32];
            u64 a0 = 0ull, a1 = 0ull, b0 = 0ull, b1 = 0ull;
#pragma unroll
            for (int c2 = 0; c2 < 16; c2++) {
                ulonglong2 wq = wk2[c2], wv = wv2[c2];
                a0 = fma2_(wq.x, xp[2 * c2], a0); a1 = fma2_(wq.y, xp[2 * c2 + 1], a1);
                b0 = fma2_(wv.x, xp[2 * c2], b0); b1 = fma2_(wv.y, xp[2 * c2 + 1], b1);
            }
            kp[d] = add2_(a0, a1); vp[d] = add2_(b0, b1);
        }
        {
            float v0[4], v1[4];
#pragma unroll
            for (int e = 0; e < 4; e++) upk2(vp[e], v0[e], v1[e]);
            *(float4*)(vg0 + h * 4) = make_float4(v0[0], v0[1], v0[2], v0[3]);
            *(float4*)(vg0 + 32 + h * 4) = make_float4(v1[0], v1[1], v1[2], v1[3]);
        }
        u64 ss = mul2_(kp[0], kp[0]);
        ss = fma2_(kp[1], kp[1], ss); ss = fma2_(kp[2], kp[2], ss); ss = fma2_(kp[3], kp[3], ss);
        float s0, s1; upk2(ss, s0, s1);
        u64 knp = pk2(rsqrtf(s0), rsqrtf(s1));
        u64 kh[4];
#pragma unroll
        for (int d = 0; d < 4; d++) kh[d] = mul2_(kp[d], knp);
        float p[16];
#pragma unroll
        for (int d = 0; d < 4; d++)
#pragma unroll
            for (int e = 0; e < 4; e++) {
                float a, bb; upk2(mul2_(kh[d], vp[e]), a, bb);
                p[d * 4 + e] = a + bb;
            }
#pragma unroll
        for (int i = 0; i < 16; i++) {
            p[i] += __shfl_xor_sync(0xffffffffu, p[i], 16);
            p[i] += __shfl_xor_sync(0xffffffffu, p[i], 8);
            p[i] += __shfl_xor_sync(0xffffffffu, p[i], 4);
        }
        if (lane < 4) {
#pragma unroll
            for (int i = 0; i < 16; i++) accsh[warp][lane][h][i] = p[i];
        }
    }
    __syncthreads();
    {
        const int h = tid >> 4, de = tid & 15;
        float s = 0.f;
#pragma unroll
        for (int w = 0; w < 4; w++)
#pragma unroll
            for (int sb = 0; sb < 4; sb++) s += accsh[w][sb][h][de];
        g_part_la[(size_t)(b * NCH + ch) * 128 + tid] = s;
    }
}

// ---------------- K2: LA pass2 — c-outer q GEMM from STAGED x tile ----------------
#define LA2_SMEM 55840
__global__ __launch_bounds__(128) void k_la_pass2(const float* __restrict__ rgb,
                                                  const float* __restrict__ qkvw,
                                                  const float* __restrict__ pw,
                                                  const float* __restrict__ pb,
                                                  const float* __restrict__ dw) {
    extern __shared__ __align__(16) char dynsm[];
    u64* qTdup = (u64*)dynsm;                      // 8192B
    u64* projdup = qTdup + 1024;                   // -> 16384
    u64* attn_dup = projdup + 1024;                // -> 17408
    float* region = (float*)(dynsm + 17408);       // 38016B: x tile -> v halo -> pool
    float* dwsh = (float*)(dynsm + 55424);         // 72
    float* pbsh = (float*)(dynsm + 55712);         // 32
    const int b = blockIdx.y, ch = blockIdx.x, tid = threadIdx.x;
    const int warp = tid >> 5, lane = tid & 31;
    for (int i = tid; i < 1024; i += 128) {
        float a = qkvw[(i & 31) * 32 + (i >> 5)];  // qT[c][r]
        qTdup[i] = pk2(a, a);
        float p_ = pw[i]; projdup[i] = pk2(p_, p_);
    }
    {
        float s = 0.f;
        for (int c2 = 0; c2 < NCH; c2++) s += g_part_la[(size_t)(b * NCH + c2) * 128 + tid];
        attn_dup[tid] = pk2(s, s);
    }
    if (tid < 72) dwsh[tid] = dw[tid];
    if (tid < 32) pbsh[tid] = pb[tid];
    const int l0b = ch * CHK;
    {   // phase A: stage x tile (32x256)
        const float* xr = rgb + (size_t)b * CN * LN + l0b;
        for (int i = tid; i < 2048; i += 128) {
            int c = i >> 6, p4 = i & 63;
            *(float4*)(region + c * 256 + p4 * 4) = *(const float4*)(xr + (size_t)c * LN + p4 * 4);
        }
    }
    __syncthreads();
    const int l0 = l0b + 2 * tid;
    u64 q[32];
#pragma unroll
    for (int r = 0; r < 32; r++) q[r] = 0ull;
#pragma unroll 4
    for (int c = 0; c < 32; c++) {
        u64 xc = *(const u64*)(region + c * 256 + 2 * tid);
        const ulonglong2* wt = (const ulonglong2*)&qTdup[c * 32];
#pragma unroll
        for (int j2 = 0; j2 < 16; j2++) {
            ulonglong2 w = wt[j2];
            q[2 * j2] = fma2_(w.x, xc, q[2 * j2]);
            q[2 * j2 + 1] = fma2_(w.y, xc, q[2 * j2 + 1]);
        }
    }
    __syncthreads();
    // phase B: stage v halo (264 x 36)
    for (int i = tid; i < 264 * 8; i += 128) {
        int r = i >> 3, c4 = i & 7;
        int gl = l0b - 4 + r;
        float4 v = (gl >= 0 && gl < LN) ? *(const float4*)(g_vbuf + ((size_t)b * LN + gl) * 32 + c4 * 4)
                                        : make_float4(0.f, 0.f, 0.f, 0.f);
        *(float4*)(region + r * 36 + c4 * 4) = v;
    }
    __syncthreads();
    const u64 HALFP = pk2(0.5f, 0.5f);
    u64 outp[32];
#pragma unroll
    for (int h = 0; h < HEADSN; h++) {
        u64* qh = &q[h * 4];
        u64 ss = mul2_(qh[0], qh[0]);
        ss = fma2_(qh[1], qh[1], ss); ss = fma2_(qh[2], qh[2], ss); ss = fma2_(qh[3], qh[3], ss);
        float s0, s1; upk2(ss, s0, s1);
        u64 qnp = pk2(rsqrtf(s0) * INV_PI, rsqrtf(s1) * INV_PI);
        float dc0[4] = {0.f, 0.f, 0.f, 0.f}, dc1[4] = {0.f, 0.f, 0.f, 0.f};
        u64 vcp[4];
        float4 aR = *(float4*)(region + (2 * tid) * 36 + h * 4);
#pragma unroll
        for (int t9 = 0; t9 < 9; t9++) {
            float4 nb = *(float4*)(region + (2 * tid + t9 + 1) * 36 + h * 4);
            float wd = dwsh[h * 9 + t9];
            dc0[0] += wd * aR.x; dc0[1] += wd * aR.y; dc0[2] += wd * aR.z; dc0[3] += wd * aR.w;
            dc1[0] += wd * nb.x; dc1[1] += wd * nb.y; dc1[2] += wd * nb.z; dc1[3] += wd * nb.w;
            if (t9 == 4) {
                vcp[0] = pk2(aR.x, nb.x); vcp[1] = pk2(aR.y, nb.y);
                vcp[2] = pk2(aR.z, nb.z); vcp[3] = pk2(aR.w, nb.w);
            }
            aR = nb;
        }
#pragma unroll
        for (int e = 0; e < 4; e++) {
            u64 t = mul2_(qh[0], attn_dup[h * 16 + e]);
            t = fma2_(qh[1], attn_dup[h * 16 + 4 + e], t);
            t = fma2_(qh[2], attn_dup[h * 16 + 8 + e], t);
            t = fma2_(qh[3], attn_dup[h * 16 + 12 + e], t);
            outp[h * 4 + e] = fma2_(qnp, t, mul2_(HALFP, vcp[e]));
        }
        u64 os = mul2_(outp[h * 4], outp[h * 4]);
        os = fma2_(outp[h * 4 + 1], outp[h * 4 + 1], os);
        os = fma2_(outp[h * 4 + 2], outp[h * 4 + 2], os);
        os = fma2_(outp[h * 4 + 3], outp[h * 4 + 3], os);
        float o0, o1; upk2(os, o0, o1);
        u64 onp = pk2(rsqrtf(o0), rsqrtf(o1));
#pragma unroll
        for (int e = 0; e < 4; e++)
            outp[h * 4 + e] = fma2_(outp[h * 4 + e], onp, pk2(dc0[e], dc1[e]));
    }
    __syncthreads();            // halo dead -> pool partial buffer
    float* psum = region;
    float* pmax = region + 512;
#pragma unroll
    for (int c = 0; c < 32; c++) {
        const ulonglong2* w2 = (const ulonglong2*)&projdup[c * 32];
        u64 a0 = pk2(pbsh[c], pbsh[c]), a1 = 0ull;
#pragma unroll
        for (int j2 = 0; j2 < 16; j2++) {
            ulonglong2 w = w2[j2];
            a0 = fma2_(w.x, outp[2 * j2], a0); a1 = fma2_(w.y, outp[2 * j2 + 1], a1);
        }
        u64 a = add2_(a0, a1);
        *(u64*)(g_f1 + (size_t)b * CN * LN + (size_t)c * LN + l0) = a;
        float s0, s1; upk2(a, s0, s1);
        float sc = s0 + s1, mc = fmaxf(s0, s1);
        sc += __shfl_xor_sync(0xffffffffu, sc, 16); mc = fmaxf(mc, __shfl_xor_sync(0xffffffffu, mc, 16));
        sc += __shfl_xor_sync(0xffffffffu, sc, 8);  mc = fmaxf(mc, __shfl_xor_sync(0xffffffffu, mc, 8));
        sc += __shfl_xor_sync(0xffffffffu, sc, 4);  mc = fmaxf(mc, __shfl_xor_sync(0xffffffffu, mc, 4));
        if (lane < 4) { psum[(warp * 4 + lane) * 32 + c] = sc; pmax[(warp * 4 + lane) * 32 + c] = mc; }
    }
    __syncthreads();
    if (tid < 32) {
        float s = 0.f, m = -1e30f;
#pragma unroll
        for (int k = 0; k < 16; k++) { s += psum[k * 32 + tid]; m = fmaxf(m, pmax[k * 32 + tid]); }
        g_pf_sum[((size_t)b * NCH + ch) * 32 + tid] = s;
        g_pf_max[((size_t)b * NCH + ch) * 32 + tid] = m;
    }
}

// ---------------- K3: XCA pass1 — q.k Gram + norm partials (R8-proven) ----------------
__global__ __launch_bounds__(128) void k_xca_pass1(const float* __restrict__ freq,
                                                   const float* __restrict__ qkvw) {
    __shared__ __align__(16) u64 wdup[64 * 32];
    __shared__ float accsh[4][4][HEADSN][24];
    const int b = blockIdx.y, ch = blockIdx.x, tid = threadIdx.x;
    const int warp = tid >> 5, lane = tid & 31;
    for (int i = tid; i < 64 * 32; i += 128) { float w = qkvw[i]; wdup[i] = pk2(w, w); }
    __syncthreads();
    const int l0 = ch * CHK + 2 * tid;
    const float* xr = freq + (size_t)b * CN * LN;
    u64 xp[32];
#pragma unroll
    for (int c = 0; c < 32; c++) xp[c] = *(const u64*)(xr + (size_t)c * LN + l0);
#pragma unroll
    for (int h = 0; h < HEADSN; h++) {
        u64 qp[4], kp[4];
#pragma unroll
        for (int d = 0; d < 4; d++) {
            const ulonglong2* wq2 = (const ulonglong2*)&wdup[(h * 4 + d) * 32];
            const ulonglong2* wk2 = (const ulonglong2*)&wdup[(32 + h * 4 + d) * 32];
            u64 a0 = 0ull, a1 = 0ull, b0 = 0ull, b1 = 0ull;
#pragma unroll
            for (int c2 = 0; c2 < 16; c2++) {
                ulonglong2 wq = wq2[c2], wk = wk2[c2];
                a0 = fma2_(wq.x, xp[2 * c2], a0); a1 = fma2_(wq.y, xp[2 * c2 + 1], a1);
                b0 = fma2_(wk.x, xp[2 * c2], b0); b1 = fma2_(wk.y, xp[2 * c2 + 1], b1);
            }
            qp[d] = add2_(a0, a1); kp[d] = add2_(b0, b1);
        }
        float p[24];
#pragma unroll
        for (int d = 0; d < 4; d++)
#pragma unroll
            for (int e = 0; e < 4; e++) {
                float a, bb; upk2(mul2_(qp[d], kp[e]), a, bb);
                p[d * 4 + e] = a + bb;
            }
#pragma unroll
        for (int d = 0; d < 4; d++) {
            float a, bb;
            upk2(mul2_(qp[d], qp[d]), a, bb); p[16 + d] = a + bb;
            upk2(mul2_(kp[d], kp[d]), a, bb); p[20 + d] = a + bb;
        }
#pragma unroll
        for (int i = 0; i < 24; i++) {
            p[i] += __shfl_xor_sync(0xffffffffu, p[i], 16);
            p[i] += __shfl_xor_sync(0xffffffffu, p[i], 8);
            p[i] += __shfl_xor_sync(0xffffffffu, p[i], 4);
        }
        if (lane < 4) {
#pragma unroll
            for (int i = 0; i < 24; i++) accsh[warp][lane][h][i] = p[i];
        }
    }
    __syncthreads();
    for (int i = tid; i < HEADSN * 24; i += 128) {
        const int h = i / 24, j = i % 24;
        float s = 0.f;
#pragma unroll
        for (int w = 0; w < 4; w++)
#pragma unroll
            for (int sb = 0; sb < 4; sb++) s += accsh[w][sb][h][j];
        g_part_x[((size_t)(b * NCH + ch) * HEADSN + h) * 24 + j] = s;
    }
}

// ---------------- K4: XCA pass2 — c-outer v GEMM from STAGED x tile ----------------
#define XCA2_SMEM 50304
__global__ __launch_bounds__(128) void k_xca_pass2(const float* __restrict__ freq,
                                                   const float* __restrict__ qkvw,
                                                   const float* __restrict__ pw,
                                                   const float* __restrict__ pb,
                                                   const float* __restrict__ temp) {
    extern __shared__ __align__(16) char dynsm4[];
    u64* vTdup = (u64*)dynsm4;                     // 8192B
    u64* projdup = vTdup + 1024;                   // -> 16384
    u64* attn_dup = projdup + 1024;                // -> 17408
    float* pbsh = (float*)(dynsm4 + 17408);        // -> 17536
    float* xsh = (float*)(dynsm4 + 17536);         // 32768B -> 50304
    const int b = blockIdx.y, ch = blockIdx.x, tid = threadIdx.x;
    const int warp = tid >> 5, lane = tid & 31;
    for (int i = tid; i < 1024; i += 128) {
        float a = qkvw[64 * 32 + (i & 31) * 32 + (i >> 5)];  // vT[c][r]
        vTdup[i] = pk2(a, a);
        float p_ = pw[i]; projdup[i] = pk2(p_, p_);
    }
    if (tid < 32) pbsh[tid] = pb[tid];
    if (tid < 32) {   // folded attn softmax: one thread per (h,d)
        const int h = tid >> 2, d = tid & 3;
        const float* base = g_part_x + (size_t)b * NCH * 192 + h * 24;
        float qk[4] = {0.f, 0.f, 0.f, 0.f}, qq = 0.f, kk[4] = {0.f, 0.f, 0.f, 0.f};
        for (int c2 = 0; c2 < NCH; c2++) {
            const float* pc = base + (size_t)c2 * 192;
            qk[0] += pc[d * 4 + 0]; qk[1] += pc[d * 4 + 1]; qk[2] += pc[d * 4 + 2]; qk[3] += pc[d * 4 + 3];
            qq += pc[16 + d];
            kk[0] += pc[20]; kk[1] += pc[21]; kk[2] += pc[22]; kk[3] += pc[23];
        }
        float nq = fmaxf(sqrtf(qq), 1e-12f);
        float t = temp[h];
        float a[4], m = -1e30f;
#pragma unroll
        for (int e = 0; e < 4; e++) {
            a[e] = qk[e] / (nq * fmaxf(sqrtf(kk[e]), 1e-12f)) * t;
            m = fmaxf(m, a[e]);
        }
        float sum = 0.f;
#pragma unroll
        for (int e = 0; e < 4; e++) { a[e] = expf(a[e] - m); sum += a[e]; }
        float inv = 1.f / sum;
#pragma unroll
        for (int e = 0; e < 4; e++) {
            float v = a[e] * inv;
            attn_dup[h * 16 + d * 4 + e] = pk2(v, v);
        }
    }
    const int l0b = ch * CHK;
    {
        const float* xr = freq + (size_t)b * CN * LN + l0b;
        for (int i = tid; i < 2048; i += 128) {
            int c = i >> 6, p4 = i & 63;
            *(float4*)(xsh + c * 256 + p4 * 4) = *(const float4*)(xr + (size_t)c * LN + p4 * 4);
        }
    }
    __syncthreads();
    const int l0 = l0b + 2 * tid;
    u64 vac[32];
#pragma unroll
    for (int r = 0; r < 32; r++) vac[r] = 0ull;
#pragma unroll 4
    for (int c = 0; c < 32; c++) {
        u64 xc = *(const u64*)(xsh + c * 256 + 2 * tid);
        const ulonglong2* wt = (const ulonglong2*)&vTdup[c * 32];
#pragma unroll
        for (int j2 = 0; j2 < 16; j2++) {
            ulonglong2 w = wt[j2];
            vac[2 * j2] = fma2_(w.x, xc, vac[2 * j2]);
            vac[2 * j2 + 1] = fma2_(w.y, xc, vac[2 * j2 + 1]);
        }
    }
    u64 outp[32];
#pragma unroll
    for (int h = 0; h < HEADSN; h++) {
#pragma unroll
        for (int d = 0; d < 4; d++) {
            u64 o = mul2_(attn_dup[h * 16 + d * 4 + 0], vac[h * 4 + 0]);
            o = fma2_(attn_dup[h * 16 + d * 4 + 1], vac[h * 4 + 1], o);
            o = fma2_(attn_dup[h * 16 + d * 4 + 2], vac[h * 4 + 2], o);
            o = fma2_(attn_dup[h * 16 + d * 4 + 3], vac[h * 4 + 3], o);
            outp[h * 4 + d] = o;
        }
    }
    __syncthreads();        // x dead -> pool partial buffer overlays xsh
    float* psum = xsh;
    float* pmax = xsh + 512;
#pragma unroll
    for (int c = 0; c < 32; c++) {
        const ulonglong2* w2 = (const ulonglong2*)&projdup[c * 32];
        u64 a0 = pk2(pbsh[c], pbsh[c]), a1 = 0ull;
#pragma unroll
        for (int j2 = 0; j2 < 16; j2++) {
            ulonglong2 w = w2[j2];
            a0 = fma2_(w.x, outp[2 * j2], a0); a1 = fma2_(w.y, outp[2 * j2 + 1], a1);
        }
        u64 a = add2_(a0, a1);
        *(u64*)(g_f2 + (size_t)b * CN * LN + (size_t)c * LN + l0) = a;
        float s0, s1; upk2(a, s0, s1);
        float sc = s0 + s1, mc = fmaxf(s0, s1);
        sc += __shfl_xor_sync(0xffffffffu, sc, 16); mc = fmaxf(mc, __shfl_xor_sync(0xffffffffu, mc, 16));
        sc += __shfl_xor_sync(0xffffffffu, sc, 8);  mc = fmaxf(mc, __shfl_xor_sync(0xffffffffu, mc, 8));
        sc += __shfl_xor_sync(0xffffffffu, sc, 4);  mc = fmaxf(mc, __shfl_xor_sync(0xffffffffu, mc, 4));
        if (lane < 4) { psum[(warp * 4 + lane) * 32 + c] = sc; pmax[(warp * 4 + lane) * 32 + c] = mc; }
    }
    __syncthreads();
    if (tid < 32) {
        float s = 0.f, m = -1e30f;
#pragma unroll
        for (int k = 0; k < 16; k++) { s += psum[k * 32 + tid]; m = fmaxf(m, pmax[k * 32 + tid]); }
        g_pf_sum[(size_t)(BN * NCH * 32) + ((size_t)b * NCH + ch) * 32 + tid] = s;
        g_pf_max[(size_t)(BN * NCH * 32) + ((size_t)b * NCH + ch) * 32 + tid] = m;
    }
}

// ---------------- K5: channel MLPs + cross softmax ----------------
__global__ void k_cafm_vec(const float* __restrict__ a1w, const float* __restrict__ a1b,
                           const float* __restrict__ m1w, const float* __restrict__ m1b,
                           const float* __restrict__ a2w, const float* __restrict__ a2b,
                           const float* __restrict__ m2w, const float* __restrict__ m2b,
                           const float* __restrict__ a11w, const float* __restrict__ a11b,
                           const float* __restrict__ m11w, const float* __restrict__ m11b,
                           const float* __restrict__ a22w, const float* __restrict__ a22b,
                           const float* __restrict__ m22w, const float* __restrict__ m22b) {
    const int b = blockIdx.x, c = threadIdx.x;
    __shared__ float av1[32], mx1[32], av2[32], mx2[32];
    __shared__ float h1a[16], h1m[16], h2a[16], h2m[16];
    __shared__ float a1s[32], a2s[32];
    {
        float s1 = 0.f, m1 = -1e30f, s2 = 0.f, m2 = -1e30f;
        for (int chn = 0; chn < NCH; chn++) {
            s1 += g_pf_sum[((size_t)b * NCH + chn) * 32 + c];
            m1 = fmaxf(m1, g_pf_max[((size_t)b * NCH + chn) * 32 + c]);
            s2 += g_pf_sum[(size_t)(BN * NCH * 32) + ((size_t)b * NCH + chn) * 32 + c];
            m2 = fmaxf(m2, g_pf_max[(size_t)(BN * NCH * 32) + ((size_t)b * NCH + chn) * 32 + c]);
        }
        av1[c] = s1 * (1.f / LN); mx1[c] = m1;
        av2[c] = s2 * (1.f / LN); mx2[c] = m2;
    }
    __syncthreads();
    if (c < 16) {
        float s1 = a1b[c], s2 = m1b[c], s3 = a2b[c], s4 = m2b[c];
        for (int j = 0; j < 32; j++) {
            s1 += a1w[c * 32 + j] * av1[j];
            s2 += m1w[c * 32 + j] * mx1[j];
            s3 += a2w[c * 32 + j] * av2[j];
            s4 += m2w[c * 32 + j] * mx2[j];
        }
        h1a[c] = fmaxf(s1, 0.f); h1m[c] = fmaxf(s2, 0.f);
        h2a[c] = fmaxf(s3, 0.f); h2m[c] = fmaxf(s4, 0.f);
    }
    __syncthreads();
    {
        float s1 = a11b[c] + m11b[c];
        float s2 = a22b[c] + m22b[c];
        for (int j = 0; j < 16; j++) {
            s1 += a11w[c * 16 + j] * h1a[j] + m11w[c * 16 + j] * h1m[j];
            s2 += a22w[c * 16 + j] * h2a[j] + m22w[c * 16 + j] * h2m[j];
        }
        a1s[c] = s1; a2s[c] = s2;
    }
    __syncthreads();
    {
        float ac = a1s[c], m = -1e30f;
        for (int d = 0; d < 32; d++) m = fmaxf(m, ac * a2s[d]);
        float sum = 0.f;
        for (int d = 0; d < 32; d++) sum += expf(ac * a2s[d] - m);
        float inv = 1.f / sum;
        for (int d = 0; d < 32; d++) g_s1[(size_t)b * 1024 + c * 32 + d] = expf(ac * a2s[d] - m) * inv;
    }
    {
        float ac = a2s[c], m = -1e30f;
        for (int d = 0; d < 32; d++) m = fmaxf(m, ac * a1s[d]);
        float sum = 0.f;
        for (int d = 0; d < 32; d++) sum += expf(ac * a1s[d] - m);
        float inv = 1.f / sum;
        for (int d = 0; d < 32; d++) g_s2[(size_t)b * 1024 + c * 32 + d] = expf(ac * a1s[d] - m) * inv;
    }
}

// ---------------- K6: fused s@f + mean/max over C, STAGED f tile ----------------
#define GP_SMEM (8192 + 32768)
__global__ __launch_bounds__(128) void k_gate_pool() {
    extern __shared__ __align__(16) char sm5[];
    u64* sTd = (u64*)sm5;                          // 8192B
    float* fbuf = (float*)(sm5 + 8192);            // 32768B
    const int b = blockIdx.y, ch = blockIdx.x, tid = threadIdx.x;
    const int l0b = ch * CHK;
    const int l0 = l0b + 2 * tid;
    const float* srcs[2] = { g_f1 + (size_t)b * CN * LN + l0b, g_f2 + (size_t)b * CN * LN + l0b };
    const float* wsrc[2] = { g_s1 + (size_t)b * 1024, g_s2 + (size_t)b * 1024 };
    float* dsts[2] = { g_pooled1 + (size_t)b * 2 * LN, g_pooled2 + (size_t)b * 2 * LN };
#pragma unroll
    for (int br = 0; br < 2; br++) {
        for (int i = tid; i < 2048; i += 128) {
            int c = i >> 6, p4 = i & 63;
            *(float4*)(fbuf + c * 256 + p4 * 4) = *(const float4*)(srcs[br] + (size_t)c * LN + p4 * 4);
        }
        for (int i = tid; i < 1024; i += 128) {
            float a = wsrc[br][(i & 31) * 32 + (i >> 5)];   // sT[d][c] = s[c][d]
            sTd[i] = pk2(a, a);
        }
        __syncthreads();
        u64 acc[32];
#pragma unroll
        for (int c = 0; c < 32; c++) acc[c] = 0ull;
#pragma unroll 4
        for (int d = 0; d < 32; d++) {
            u64 fd = *(const u64*)(fbuf + d * 256 + 2 * tid);
            const ulonglong2* sp = (const ulonglong2*)&sTd[d * 32];
#pragma unroll
            for (int c2 = 0; c2 < 16; c2++) {
                ulonglong2 w = sp[c2];
                acc[2 * c2] = fma2_(w.x, fd, acc[2 * c2]);
                acc[2 * c2 + 1] = fma2_(w.y, fd, acc[2 * c2 + 1]);
            }
        }
        u64 sump = 0ull;
        float mx0 = -1e30f, mx1 = -1e30f;
#pragma unroll
        for (int c = 0; c < 32; c++) {
            sump = add2_(sump, acc[c]);
            float v0, v1; upk2(acc[c], v0, v1);
            mx0 = fmaxf(mx0, v0); mx1 = fmaxf(mx1, v1);
        }
        *(u64*)(dsts[br] + l0) = mul2_(sump, pk2(1.f / 32.f, 1.f / 32.f));
        *(u64*)(dsts[br] + LN + l0) = pk2(mx0, mx1);
        __syncthreads();
    }
}

// ---------------- K7: fused conv1 + conv2 + softmax stats ----------------
__global__ __launch_bounds__(256) void k_gate_conv(const float* __restrict__ c1w, const float* __restrict__ c1b,
                                                   const float* __restrict__ c2w, const float* __restrict__ c2b) {
    const int b = blockIdx.x, gate = blockIdx.y, tid = threadIdx.x;
    __shared__ float y1s[LN];
    __shared__ float red[256];
    const float* pin = (gate ? g_pooled2 : g_pooled1) + (size_t)b * 2 * LN;
    float* yo = (gate ? g_y2b : g_y2a) + (size_t)b * LN;
    float w1[18];
#pragma unroll
    for (int i = 0; i < 18; i++) w1[i] = c1w[i];
    float b1 = c1b[0];
    float w2[9];
#pragma unroll
    for (int i = 0; i < 9; i++) w2[i] = c2w[i];
    float b2 = c2b[0];
    for (int p = tid; p < LN; p += 256) {
        int hh = p / WN, ww = p % WN;
        float acc = b1;
#pragma unroll
        for (int ci = 0; ci < 2; ci++)
#pragma unroll
            for (int kh = 0; kh < 3; kh++) {
                int ih = hh + kh - 1;
                if (ih < 0 || ih >= HN) continue;
#pragma unroll
                for (int kw = 0; kw < 3; kw++) {
                    int iw = ww + kw - 1;
                    if (iw < 0 || iw >= WN) continue;
                    acc += pin[(size_t)ci * LN + ih * WN + iw] * w1[(ci * 3 + kh) * 3 + kw];
                }
            }
        y1s[p] = fmaxf(acc, 0.f);
    }
    __syncthreads();
    float yl[25];
    float mloc = -1e30f;
    int idx = 0;
    for (int p = tid; p < LN; p += 256, idx++) {
        int hh = p / WN, ww = p % WN;
        float acc = b2;
#pragma unroll
        for (int kh = 0; kh < 3; kh++) {
            int ih = hh + kh - 1;
            if (ih < 0 || ih >= HN) continue;
#pragma unroll
            for (int kw = 0; kw < 3; kw++) {
                int iw = ww + kw - 1;
                if (iw < 0 || iw >= WN) continue;
                acc += y1s[ih * WN + iw] * w2[kh * 3 + kw];
            }
        }
        yo[p] = acc;
        yl[idx] = acc;
        mloc = fmaxf(mloc, acc);
    }
    red[tid] = mloc;
    __syncthreads();
    for (int o = 128; o > 0; o >>= 1) { if (tid < o) red[tid] = fmaxf(red[tid], red[tid + o]); __syncthreads(); }
    float gm = red[0];
    __syncthreads();
    float sloc = 0.f;
#pragma unroll
    for (int i = 0; i < 25; i++) sloc += expf(yl[i] - gm);
    red[tid] = sloc;
    __syncthreads();
    for (int o = 128; o > 0; o >>= 1) { if (tid < o) red[tid] += red[tid + o]; __syncthreads(); }
    if (tid == 0) { g_gstat[(b * 2 + gate) * 2] = gm; g_gstat[(b * 2 + gate) * 2 + 1] = red[0]; }
}

// ---------------- K8: final gated residual combine ----------------
__global__ __launch_bounds__(256) void k_final(float* __restrict__ out) {
    const int NT4 = BN * CN * LN / 4;
    int i4 = blockIdx.x * 256 + threadIdx.x;
    if (i4 >= NT4) return;
    size_t i = (size_t)i4 * 4;
    int b = (int)(i / (CN * LN));
    int rem = (int)(i - (size_t)b * CN * LN);
    int l = rem % LN;
    float4 f1v = *(const float4*)(g_f1 + i);
    float4 f2v = *(const float4*)(g_f2 + i);
    float4 y1v = *(const float4*)(g_y2a + (size_t)b * LN + l);
    float4 y2v = *(const float4*)(g_y2b + (size_t)b * LN + l);
    float m1 = g_gstat[b * 4 + 0], s1i = 1.f / g_gstat[b * 4 + 1];
    float m2 = g_gstat[b * 4 + 2], s2i = 1.f / g_gstat[b * 4 + 3];
    float4 o;
    o.x = f1v.x * (1.f + expf(y1v.x - m1) * s1i) + f2v.x * (1.f + expf(y2v.x - m2) * s2i);
    o.y = f1v.y * (1.f + expf(y1v.y - m1) * s1i) + f2v.y * (1.f + expf(y2v.y - m2) * s2i);
    o.z = f1v.z * (1.f + expf(y1v.z - m1) * s1i) + f2v.z * (1.f + expf(y2v.z - m2) * s2i);
    o.w = f1v.w * (1.f + expf(y1v.w - m1) * s1i) + f2v.w * (1.f + expf(y2v.w - m2) * s2i);
    *(float4*)(out + i) = o;
}

// ---------------- launch ----------------
extern "C" void kernel_launch(void* const* d_in, const int* in_sizes, int n_in,
                              void* d_out, int out_size) {
    const float* rgb     = (const float*)d_in[0];
    const float* freq    = (const float*)d_in[1];
    const float* la_qkv  = (const float*)d_in[2];
    const float* la_pw   = (const float*)d_in[3];
    const float* la_pb   = (const float*)d_in[4];
    const float* la_dw   = (const float*)d_in[5];
    const float* xa_qkv  = (const float*)d_in[6];
    const float* xa_temp = (const float*)d_in[7];
    const float* xa_pw   = (const float*)d_in[8];
    const float* xa_pb   = (const float*)d_in[9];
    const float* c1w     = (const float*)d_in[10];
    const float* c1b     = (const float*)d_in[11];
    const float* c2w     = (const float*)d_in[12];
    const float* c2b     = (const float*)d_in[13];
    const float* avg1_w  = (const float*)d_in[14];
    const float* avg1_b  = (const float*)d_in[15];
    const float* max1_w  = (const float*)d_in[16];
    const float* max1_b  = (const float*)d_in[17];
    const float* avg2_w  = (const float*)d_in[18];
    const float* avg2_b  = (const float*)d_in[19];
    const float* max2_w  = (const float*)d_in[20];
    const float* max2_b  = (const float*)d_in[21];
    const float* avg11_w = (const float*)d_in[22];
    const float* avg11_b = (const float*)d_in[23];
    const float* max11_w = (const float*)d_in[24];
    const float* max11_b = (const float*)d_in[25];
    const float* avg22_w = (const float*)d_in[26];
    const float* avg22_b = (const float*)d_in[27];
    const float* max22_w = (const float*)d_in[28];
    const float* max22_b = (const float*)d_in[29];
    float* out = (float*)d_out;

    static int smem_set = 0;
    if (!smem_set) {
        cudaFuncSetAttribute(k_la_pass2, cudaFuncAttributeMaxDynamicSharedMemorySize, LA2_SMEM);
        cudaFuncSetAttribute(k_xca_pass2, cudaFuncAttributeMaxDynamicSharedMemorySize, XCA2_SMEM);
        cudaFuncSetAttribute(k_gate_pool, cudaFuncAttributeMaxDynamicSharedMemorySize, GP_SMEM);
        smem_set = 1;
    }

    dim3 gBL(NCH, BN);
    k_la_pass1<<<gBL, 128>>>(rgb, la_qkv);
    k_xca_pass1<<<gBL, 128>>>(freq, xa_qkv);
    k_la_pass2<<<gBL, 128, LA2_SMEM>>>(rgb, la_qkv, la_pw, la_pb, la_dw);
    k_xca_pass2<<<gBL, 128, XCA2_SMEM>>>(freq, xa_qkv, xa_pw, xa_pb, xa_temp);
    k_cafm_vec<<<BN, 32>>>(avg1_w, avg1_b, max1_w, max1_b,
                           avg2_w, avg2_b, max2_w, max2_b,
                           avg11_w, avg11_b, max11_w, max11_b,
                           avg22_w, avg22_b, max22_w, max22_b);
    k_gate_pool<<<gBL, 128, GP_SMEM>>>();
    k_gate_conv<<<dim3(BN, 2), 256>>>(c1w, c1b, c2w, c2b);
    k_final<<<(BN * CN * LN / 4 + 255) / 256, 256>>>(out);
}